// round 16
// baseline (speedup 1.0000x reference)
#include <cuda_runtime.h>
#include <cuda_fp16.h>
#include <cstdint>

#define E_   8
#define CAP_ 2048
#define D_   1024
#define H_   4096

// ---------------- scratch (device globals; no runtime allocation) ----------------
__device__ __half g_Xh [(size_t)E_ * CAP_ * D_];   // [E*2048][1024]
__device__ __half g_W1h[(size_t)E_ * H_   * D_];   // [E*4096][1024]
__device__ __half g_W2T[(size_t)E_ * D_   * H_];   // [E*1024][4096]  (W2^T)
__device__ __half g_Y  [(size_t)E_ * CAP_ * H_];   // [E*2048][4096]

// ---------------- PTX helpers (portable: sm_80+ features only) ----------------
__device__ __forceinline__ uint32_t smem_u32(const void* p) {
    uint32_t a;
    asm("{ .reg .u64 t; cvta.to.shared.u64 t, %1; cvt.u32.u64 %0, t; }" : "=r"(a) : "l"(p));
    return a;
}
__device__ __forceinline__ void cpa16(uint32_t s, const void* g) {
    asm volatile("cp.async.cg.shared.global [%0], [%1], 16;" :: "r"(s), "l"(g) : "memory");
}
__device__ __forceinline__ void ldsm4(uint32_t r[4], uint32_t addr) {
    asm volatile("ldmatrix.sync.aligned.m8n8.x4.shared.b16 {%0,%1,%2,%3}, [%4];"
                 : "=r"(r[0]), "=r"(r[1]), "=r"(r[2]), "=r"(r[3]) : "r"(addr));
}
__device__ __forceinline__ void mma16816(float d[4], const uint32_t a[4],
                                         uint32_t b0, uint32_t b1) {
    asm volatile("mma.sync.aligned.m16n8k16.row.col.f32.f16.f16.f32 "
                 "{%0,%1,%2,%3},{%4,%5,%6,%7},{%8,%9},{%0,%1,%2,%3};"
                 : "+f"(d[0]), "+f"(d[1]), "+f"(d[2]), "+f"(d[3])
                 : "r"(a[0]), "r"(a[1]), "r"(a[2]), "r"(a[3]), "r"(b0), "r"(b1));
}
__device__ __forceinline__ uint32_t h2u(__half2 h) {
    return *reinterpret_cast<uint32_t*>(&h);
}

// ---------------- convert: fp32 -> fp16 elementwise, element-offset variant ----------
template<int TGT>   // 0 -> g_Xh, 1 -> g_W1h
__global__ void conv_f16(const float* __restrict__ src, size_t dstoff) {
    __half* dst = ((TGT == 0) ? g_Xh : g_W1h) + dstoff;
    size_t t = (size_t)blockIdx.x * 256 + threadIdx.x;   // one float4 per thread
    float4 v = *((const float4*)src + t);
    __half2 h0 = __floats2half2_rn(v.x, v.y);
    __half2 h1 = __floats2half2_rn(v.z, v.w);
    *(uint2*)(dst + t * 4) = make_uint2(h2u(h0), h2u(h1));
}

// ---------------- W2 transpose + convert, 64-thread blocks ----------------
__global__ void __launch_bounds__(64) conv_w2t(const float* __restrict__ w2) {
    __shared__ float tile[32][33];
    int e  = blockIdx.z;
    int d0 = blockIdx.x * 32;
    int h0 = blockIdx.y * 32;
    int tx = threadIdx.x, ty = threadIdx.y;              // (32, 2)
#pragma unroll
    for (int r = 0; r < 16; r++) {
        int h = h0 + ty + r * 2;
        tile[ty + r * 2][tx] = w2[((size_t)(e * H_ + h)) * D_ + d0 + tx];
    }
    __syncthreads();
#pragma unroll
    for (int r = 0; r < 16; r++) {
        int d = d0 + ty + r * 2;
        int h = h0 + tx;
        g_W2T[((size_t)(e * D_ + d)) * H_ + h] = __float2half_rn(tile[tx][ty + r * 2]);
    }
}

// ---------------- fp16 GEMM via mma.sync (cp.async pipeline), R8 engine ----------------
// 128x128 CTA tile, 4 warps (2x2) of 64x64 warp tiles, 128 threads,
// 3 stages (96 KB smem) -> 2 CTAs/SM.  `ebase` = first expert of this launch.
#define TM 128
#define TN 128
#define WM 64
#define WN 64
#define NSTAGE 3
#define STB ((TM + TN) * 128)              // 32 KB per stage
#define SMEM_TOT (NSTAGE * STB)            // 96 KB

template<int PHASE>
__global__ void __launch_bounds__(128, 2) gemm_mma(const float* __restrict__ bias,
                                                   float* __restrict__ outF,
                                                   int ebase) {
    constexpr int Ntot = (PHASE == 1) ? H_ : D_;
    constexpr int KSEG = (PHASE == 1) ? D_ : H_;
    constexpr int NCH  = KSEG / 64;        // 64-wide K chunks
    constexpr int Mt   = CAP_ / TM;
    constexpr int Nt   = Ntot / TN;
    constexpr int WROWS = WM / 16, WCOLS = WN / 8, BT16 = WN / 16;

    extern __shared__ char smem[];
    const uint32_t sb = smem_u32(smem);
    const int tid = threadIdx.x, wid = tid >> 5, lane = tid & 31;

    const int idx = blockIdx.x;
    const int mt = idx % Mt;
    const int nt = (idx / Mt) % Nt;
    const int e  = ebase + idx / (Mt * Nt);
    const int m0 = mt * TM, n0 = nt * TN;

    const __half* A = (PHASE == 1) ? g_Xh  : g_Y;
    const __half* B = (PHASE == 1) ? g_W1h : g_W2T;
    const __half* Ab = A + (size_t)(e * CAP_ + m0) * KSEG;
    const __half* Bb = B + (size_t)(e * Ntot + n0) * KSEG;

    auto issue = [&](int c) {
        const int k0 = c * 64;
        const int st = c % NSTAGE;
        const uint32_t sA = sb + st * STB, sB = sA + TM * 128;
#pragma unroll
        for (int t = 0; t < TM / 16; t++) {            // A: TM*8 chunks / 128 thr
            int i = t * 128 + tid, row = i >> 3, c16 = i & 7;
            cpa16(sA + row * 128 + ((c16 ^ (row & 7)) << 4),
                  Ab + (size_t)row * KSEG + k0 + c16 * 8);
        }
#pragma unroll
        for (int t = 0; t < TN / 16; t++) {            // B: TN*8 chunks / 128 thr
            int i = t * 128 + tid, row = i >> 3, c16 = i & 7;
            cpa16(sB + row * 128 + ((c16 ^ (row & 7)) << 4),
                  Bb + (size_t)row * KSEG + k0 + c16 * 8);
        }
        asm volatile("cp.async.commit_group;" ::: "memory");
    };

    const int m_off = (wid >> 1) * WM;     // 2x2 warp grid
    const int n_off = (wid & 1) * WN;
    float acc[WROWS][WCOLS][4] = {};

    issue(0);
    issue(1);
    asm volatile("cp.async.wait_group 1;" ::: "memory");
    __syncthreads();

    for (int c = 0; c < NCH; ++c) {
        const int st = c % NSTAGE;
        const uint32_t sA = sb + st * STB, sB = sA + TM * 128;
#pragma unroll
        for (int kk = 0; kk < 4; ++kk) {               // 4 x k16 per 64-chunk
            uint32_t aF[WROWS][4];
#pragma unroll
            for (int i = 0; i < WROWS; ++i) {
                int row = m_off + 16 * i + (lane & 15);
                int ch  = kk * 2 + (lane >> 4);
                ldsm4(aF[i], sA + row * 128 + ((ch ^ (row & 7)) << 4));
            }
            uint32_t bF[BT16][4];
#pragma unroll
            for (int j4 = 0; j4 < BT16; ++j4) {
                int row = n_off + 16 * j4 + ((lane >> 4) << 3) + (lane & 7);
                int ch  = kk * 2 + ((lane >> 3) & 1);
                ldsm4(bF[j4], sB + row * 128 + ((ch ^ (row & 7)) << 4));
            }
#pragma unroll
            for (int i = 0; i < WROWS; ++i)
#pragma unroll
                for (int j = 0; j < WCOLS; ++j)
                    mma16816(acc[i][j], aF[i], bF[j >> 1][(j & 1) * 2], bF[j >> 1][(j & 1) * 2 + 1]);
        }
        if (c + 2 < NCH) issue(c + 2);
        else asm volatile("cp.async.commit_group;" ::: "memory");
        asm volatile("cp.async.wait_group 1;" ::: "memory");
        __syncthreads();
    }

    // ---- epilogue ----
    const int r_lane = lane >> 2;
    const int c_lane = (lane & 3) * 2;
    const float* brow = bias + (size_t)e * Ntot;
#pragma unroll
    for (int i = 0; i < WROWS; ++i) {
#pragma unroll
        for (int half = 0; half < 2; ++half) {
            const int m = m0 + m_off + 16 * i + r_lane + half * 8;
            if (PHASE == 1) {
                __half* yrow = g_Y + (size_t)(e * CAP_ + m) * H_;
#pragma unroll
                for (int j = 0; j < WCOLS; ++j) {
                    const int col = n0 + n_off + 8 * j + c_lane;
                    float v0 = acc[i][j][half * 2 + 0] + brow[col];
                    float v1 = acc[i][j][half * 2 + 1] + brow[col + 1];
                    v0 = fmaxf(v0, 0.f);
                    v1 = fmaxf(v1, 0.f);
                    *(uint32_t*)(yrow + col) = h2u(__floats2half2_rn(v0, v1));
                }
            } else {
                float* orow = outF + (size_t)(e * CAP_ + m) * D_;
#pragma unroll
                for (int j = 0; j < WCOLS; ++j) {
                    const int col = n0 + n_off + 8 * j + c_lane;
                    float2 f;
                    f.x = acc[i][j][half * 2 + 0] + brow[col];
                    f.y = acc[i][j][half * 2 + 1] + brow[col + 1];
                    *(float2*)(orow + col) = f;
                }
            }
        }
    }
}

// ---------------- launch ----------------
extern "C" void kernel_launch(void* const* d_in, const int* in_sizes, int n_in,
                              void* d_out, int out_size) {
    const float* x  = (const float*)d_in[0];   // [E, CAP, D]
    const float* w1 = (const float*)d_in[1];   // [E, H, D]
    const float* b1 = (const float*)d_in[2];   // [E, H]
    const float* w2 = (const float*)d_in[3];   // [E, H, D]
    const float* b2 = (const float*)d_in[4];   // [E, D]
    float* out = (float*)d_out;                // [E, CAP, D]

    // One-time side-stream + events (resource init only; no device memory).
    static cudaStream_t s1 = nullptr;
    static cudaEvent_t  evF = nullptr, evB = nullptr, ev1A = nullptr, evG2A = nullptr;
    if (s1 == nullptr) {
        cudaStreamCreateWithFlags(&s1, cudaStreamNonBlocking);
        cudaEventCreateWithFlags(&evF,   cudaEventDisableTiming);
        cudaEventCreateWithFlags(&evB,   cudaEventDisableTiming);
        cudaEventCreateWithFlags(&ev1A,  cudaEventDisableTiming);
        cudaEventCreateWithFlags(&evG2A, cudaEventDisableTiming);
    }

    cudaFuncSetAttribute(gemm_mma<1>, cudaFuncAttributeMaxDynamicSharedMemorySize, SMEM_TOT);
    cudaFuncSetAttribute(gemm_mma<2>, cudaFuncAttributeMaxDynamicSharedMemorySize, SMEM_TOT);

    constexpr int EH = E_ / 2;                           // experts per half
    constexpr int GX_HALF = (EH * CAP_ * D_ / 4) / 256;
    constexpr int GW_HALF = (EH * H_   * D_ / 4) / 256;
    constexpr int G1_HALF = (CAP_ / TM) * (H_ / TN) * EH;   // 2048
    constexpr int G2_HALF = (CAP_ / TM) * (D_ / TN) * EH;   // 512

    // Fork side stream at graph start.
    cudaEventRecord(evF, 0);
    cudaStreamWaitEvent(s1, evF, 0);

    // main: convert experts 0-3 (X, W1) — G1A's only dependency.
    conv_f16<0><<<GX_HALF, 256>>>(x, 0);
    conv_f16<1><<<GW_HALF, 256>>>(w1, 0);

    // side: W2 transpose + convert experts 4-7 (runs alongside convA/G1A).
    conv_w2t<<<dim3(D_ / 32, H_ / 32, E_), dim3(32, 2), 0, s1>>>(w2);
    conv_f16<0><<<GX_HALF, 256, 0, s1>>>(x  + (size_t)EH * CAP_ * D_, (size_t)EH * CAP_ * D_);
    conv_f16<1><<<GW_HALF, 256, 0, s1>>>(w1 + (size_t)EH * H_   * D_, (size_t)EH * H_   * D_);
    cudaEventRecord(evB, s1);

    // main: G1A (experts 0-3), then signal side.
    gemm_mma<1><<<G1_HALF, 128, SMEM_TOT>>>(b1, nullptr, 0);
    cudaEventRecord(ev1A, 0);

    // side: G2A (experts 0-3) — co-runs with G1B, filling its wave slack.
    cudaStreamWaitEvent(s1, ev1A, 0);
    gemm_mma<2><<<G2_HALF, 128, SMEM_TOT, s1>>>(b2, out, 0);
    cudaEventRecord(evG2A, s1);

    // main: G1B (experts 4-7; needs side convB), then G2B (needs G1B + side W2T/G2A).
    cudaStreamWaitEvent(0, evB, 0);
    gemm_mma<1><<<G1_HALF, 128, SMEM_TOT>>>(b1, nullptr, EH);
    cudaStreamWaitEvent(0, evG2A, 0);
    gemm_mma<2><<<G2_HALF, 128, SMEM_TOT>>>(b2, out, EH);
}

// round 17
// speedup vs baseline: 1.0596x; 1.0596x over previous
#include <cuda_runtime.h>
#include <cuda_fp16.h>
#include <cstdint>

#define E_   8
#define CAP_ 2048
#define D_   1024
#define H_   4096

// ---------------- scratch (device globals; no runtime allocation) ----------------
__device__ __half g_Xh [(size_t)E_ * CAP_ * D_];   // [E*2048][1024]
__device__ __half g_W1h[(size_t)E_ * H_   * D_];   // [E*4096][1024]
__device__ __half g_W2T[(size_t)E_ * D_   * H_];   // [E*1024][4096]  (W2^T)
__device__ __half g_Y  [(size_t)E_ * CAP_ * H_];   // [E*2048][4096]

// ---------------- PTX helpers (portable: sm_80+ features only) ----------------
__device__ __forceinline__ uint32_t smem_u32(const void* p) {
    uint32_t a;
    asm("{ .reg .u64 t; cvta.to.shared.u64 t, %1; cvt.u32.u64 %0, t; }" : "=r"(a) : "l"(p));
    return a;
}
__device__ __forceinline__ void cpa16(uint32_t s, const void* g) {
    asm volatile("cp.async.cg.shared.global [%0], [%1], 16;" :: "r"(s), "l"(g) : "memory");
}
__device__ __forceinline__ void ldsm4(uint32_t r[4], uint32_t addr) {
    asm volatile("ldmatrix.sync.aligned.m8n8.x4.shared.b16 {%0,%1,%2,%3}, [%4];"
                 : "=r"(r[0]), "=r"(r[1]), "=r"(r[2]), "=r"(r[3]) : "r"(addr));
}
__device__ __forceinline__ void mma16816(float d[4], const uint32_t a[4],
                                         uint32_t b0, uint32_t b1) {
    asm volatile("mma.sync.aligned.m16n8k16.row.col.f32.f16.f16.f32 "
                 "{%0,%1,%2,%3},{%4,%5,%6,%7},{%8,%9},{%0,%1,%2,%3};"
                 : "+f"(d[0]), "+f"(d[1]), "+f"(d[2]), "+f"(d[3])
                 : "r"(a[0]), "r"(a[1]), "r"(a[2]), "r"(a[3]), "r"(b0), "r"(b1));
}
__device__ __forceinline__ uint32_t h2u(__half2 h) {
    return *reinterpret_cast<uint32_t*>(&h);
}

// ---------------- convert: fp32 -> fp16 elementwise, element-offset variant ----------
template<int TGT>   // 0 -> g_Xh, 1 -> g_W1h
__global__ void conv_f16(const float* __restrict__ src, size_t dstoff) {
    __half* dst = ((TGT == 0) ? g_Xh : g_W1h) + dstoff;
    size_t t = (size_t)blockIdx.x * 256 + threadIdx.x;   // one float4 per thread
    float4 v = *((const float4*)src + t);
    __half2 h0 = __floats2half2_rn(v.x, v.y);
    __half2 h1 = __floats2half2_rn(v.z, v.w);
    *(uint2*)(dst + t * 4) = make_uint2(h2u(h0), h2u(h1));
}

// ---------------- W2 transpose + convert, 64-thread blocks ----------------
__global__ void __launch_bounds__(64) conv_w2t(const float* __restrict__ w2) {
    __shared__ float tile[32][33];
    int e  = blockIdx.z;
    int d0 = blockIdx.x * 32;
    int h0 = blockIdx.y * 32;
    int tx = threadIdx.x, ty = threadIdx.y;              // (32, 2)
#pragma unroll
    for (int r = 0; r < 16; r++) {
        int h = h0 + ty + r * 2;
        tile[ty + r * 2][tx] = w2[((size_t)(e * H_ + h)) * D_ + d0 + tx];
    }
    __syncthreads();
#pragma unroll
    for (int r = 0; r < 16; r++) {
        int d = d0 + ty + r * 2;
        int h = h0 + tx;
        g_W2T[((size_t)(e * D_ + d)) * H_ + h] = __float2half_rn(tile[tx][ty + r * 2]);
    }
}

// ---------------- fp16 GEMM via mma.sync (cp.async pipeline), R8 engine ----------------
// 128x128 CTA tile, 4 warps (2x2) of 64x64 warp tiles, 128 threads,
// 3 stages (96 KB smem) -> 2 CTAs/SM.  `ebase` = first expert of this launch.
#define TM 128
#define TN 128
#define WM 64
#define WN 64
#define NSTAGE 3
#define STB ((TM + TN) * 128)              // 32 KB per stage
#define SMEM_TOT (NSTAGE * STB)            // 96 KB

template<int PHASE>
__global__ void __launch_bounds__(128, 2) gemm_mma(const float* __restrict__ bias,
                                                   float* __restrict__ outF,
                                                   int ebase) {
    constexpr int Ntot = (PHASE == 1) ? H_ : D_;
    constexpr int KSEG = (PHASE == 1) ? D_ : H_;
    constexpr int NCH  = KSEG / 64;        // 64-wide K chunks
    constexpr int Mt   = CAP_ / TM;
    constexpr int Nt   = Ntot / TN;
    constexpr int WROWS = WM / 16, WCOLS = WN / 8, BT16 = WN / 16;

    extern __shared__ char smem[];
    const uint32_t sb = smem_u32(smem);
    const int tid = threadIdx.x, wid = tid >> 5, lane = tid & 31;

    const int idx = blockIdx.x;
    const int mt = idx % Mt;
    const int nt = (idx / Mt) % Nt;
    const int e  = ebase + idx / (Mt * Nt);
    const int m0 = mt * TM, n0 = nt * TN;

    const __half* A = (PHASE == 1) ? g_Xh  : g_Y;
    const __half* B = (PHASE == 1) ? g_W1h : g_W2T;
    const __half* Ab = A + (size_t)(e * CAP_ + m0) * KSEG;
    const __half* Bb = B + (size_t)(e * Ntot + n0) * KSEG;

    auto issue = [&](int c) {
        const int k0 = c * 64;
        const int st = c % NSTAGE;
        const uint32_t sA = sb + st * STB, sB = sA + TM * 128;
#pragma unroll
        for (int t = 0; t < TM / 16; t++) {            // A: TM*8 chunks / 128 thr
            int i = t * 128 + tid, row = i >> 3, c16 = i & 7;
            cpa16(sA + row * 128 + ((c16 ^ (row & 7)) << 4),
                  Ab + (size_t)row * KSEG + k0 + c16 * 8);
        }
#pragma unroll
        for (int t = 0; t < TN / 16; t++) {            // B: TN*8 chunks / 128 thr
            int i = t * 128 + tid, row = i >> 3, c16 = i & 7;
            cpa16(sB + row * 128 + ((c16 ^ (row & 7)) << 4),
                  Bb + (size_t)row * KSEG + k0 + c16 * 8);
        }
        asm volatile("cp.async.commit_group;" ::: "memory");
    };

    const int m_off = (wid >> 1) * WM;     // 2x2 warp grid
    const int n_off = (wid & 1) * WN;
    float acc[WROWS][WCOLS][4] = {};

    issue(0);
    issue(1);
    asm volatile("cp.async.wait_group 1;" ::: "memory");
    __syncthreads();

    for (int c = 0; c < NCH; ++c) {
        const int st = c % NSTAGE;
        const uint32_t sA = sb + st * STB, sB = sA + TM * 128;
#pragma unroll
        for (int kk = 0; kk < 4; ++kk) {               // 4 x k16 per 64-chunk
            uint32_t aF[WROWS][4];
#pragma unroll
            for (int i = 0; i < WROWS; ++i) {
                int row = m_off + 16 * i + (lane & 15);
                int ch  = kk * 2 + (lane >> 4);
                ldsm4(aF[i], sA + row * 128 + ((ch ^ (row & 7)) << 4));
            }
            uint32_t bF[BT16][4];
#pragma unroll
            for (int j4 = 0; j4 < BT16; ++j4) {
                int row = n_off + 16 * j4 + ((lane >> 4) << 3) + (lane & 7);
                int ch  = kk * 2 + ((lane >> 3) & 1);
                ldsm4(bF[j4], sB + row * 128 + ((ch ^ (row & 7)) << 4));
            }
#pragma unroll
            for (int i = 0; i < WROWS; ++i)
#pragma unroll
                for (int j = 0; j < WCOLS; ++j)
                    mma16816(acc[i][j], aF[i], bF[j >> 1][(j & 1) * 2], bF[j >> 1][(j & 1) * 2 + 1]);
        }
        if (c + 2 < NCH) issue(c + 2);
        else asm volatile("cp.async.commit_group;" ::: "memory");
        asm volatile("cp.async.wait_group 1;" ::: "memory");
        __syncthreads();
    }

    // ---- epilogue ----
    const int r_lane = lane >> 2;
    const int c_lane = (lane & 3) * 2;
    const float* brow = bias + (size_t)e * Ntot;
#pragma unroll
    for (int i = 0; i < WROWS; ++i) {
#pragma unroll
        for (int half = 0; half < 2; ++half) {
            const int m = m0 + m_off + 16 * i + r_lane + half * 8;
            if (PHASE == 1) {
                __half* yrow = g_Y + (size_t)(e * CAP_ + m) * H_;
#pragma unroll
                for (int j = 0; j < WCOLS; ++j) {
                    const int col = n0 + n_off + 8 * j + c_lane;
                    float v0 = acc[i][j][half * 2 + 0] + brow[col];
                    float v1 = acc[i][j][half * 2 + 1] + brow[col + 1];
                    v0 = fmaxf(v0, 0.f);
                    v1 = fmaxf(v1, 0.f);
                    *(uint32_t*)(yrow + col) = h2u(__floats2half2_rn(v0, v1));
                }
            } else {
                float* orow = outF + (size_t)(e * CAP_ + m) * D_;
#pragma unroll
                for (int j = 0; j < WCOLS; ++j) {
                    const int col = n0 + n_off + 8 * j + c_lane;
                    float2 f;
                    f.x = acc[i][j][half * 2 + 0] + brow[col];
                    f.y = acc[i][j][half * 2 + 1] + brow[col + 1];
                    *(float2*)(orow + col) = f;
                }
            }
        }
    }
}

// ---------------- launch ----------------
extern "C" void kernel_launch(void* const* d_in, const int* in_sizes, int n_in,
                              void* d_out, int out_size) {
    const float* x  = (const float*)d_in[0];   // [E, CAP, D]
    const float* w1 = (const float*)d_in[1];   // [E, H, D]
    const float* b1 = (const float*)d_in[2];   // [E, H]
    const float* w2 = (const float*)d_in[3];   // [E, H, D]
    const float* b2 = (const float*)d_in[4];   // [E, D]
    float* out = (float*)d_out;                // [E, CAP, D]

    // One-time side-stream + events (resource init only; no device memory).
    static cudaStream_t s1 = nullptr;
    static cudaEvent_t  evA = nullptr, evB = nullptr;
    if (s1 == nullptr) {
        cudaStreamCreateWithFlags(&s1, cudaStreamNonBlocking);
        cudaEventCreateWithFlags(&evA, cudaEventDisableTiming);
        cudaEventCreateWithFlags(&evB, cudaEventDisableTiming);
    }

    cudaFuncSetAttribute(gemm_mma<1>, cudaFuncAttributeMaxDynamicSharedMemorySize, SMEM_TOT);
    cudaFuncSetAttribute(gemm_mma<2>, cudaFuncAttributeMaxDynamicSharedMemorySize, SMEM_TOT);

    constexpr int EH = E_ / 2;                           // experts per half
    constexpr int GX_HALF = (EH * CAP_ * D_ / 4) / 256;
    constexpr int GW_HALF = (EH * H_   * D_ / 4) / 256;
    constexpr int G1_HALF = (CAP_ / TM) * (H_ / TN) * EH;   // 2048
    constexpr int G2_FULL = (CAP_ / TM) * (D_ / TN) * E_;   // 1024

    // main: convA (experts 0-3, X+W1) runs SOLO at full DRAM bandwidth.
    conv_f16<0><<<GX_HALF, 256>>>(x, 0);
    conv_f16<1><<<GW_HALF, 256>>>(w1, 0);
    cudaEventRecord(evA, 0);

    // side: gated on convA completion — convB + conv_w2t are DRAM-bound and
    // execute under G1A's tensor-bound window (heterogeneous overlap only).
    cudaStreamWaitEvent(s1, evA, 0);
    conv_f16<0><<<GX_HALF, 256, 0, s1>>>(x  + (size_t)EH * CAP_ * D_, (size_t)EH * CAP_ * D_);
    conv_f16<1><<<GW_HALF, 256, 0, s1>>>(w1 + (size_t)EH * H_   * D_, (size_t)EH * H_   * D_);
    conv_w2t<<<dim3(D_ / 32, H_ / 32, E_), dim3(32, 2), 0, s1>>>(w2);
    cudaEventRecord(evB, s1);

    // main: G1A (experts 0-3) — only depends on convA.
    gemm_mma<1><<<G1_HALF, 128, SMEM_TOT>>>(b1, nullptr, 0);

    // main: G1B (experts 4-7) — needs side convB (long done by now).
    cudaStreamWaitEvent(0, evB, 0);
    gemm_mma<1><<<G1_HALF, 128, SMEM_TOT>>>(b1, nullptr, EH);

    // main: G2 monolithic (needs full g_Y + g_W2T; evB ordering covers W2T).
    gemm_mma<2><<<G2_FULL, 128, SMEM_TOT>>>(b2, out, 0);
}